// round 7
// baseline (speedup 1.0000x reference)
#include <cuda_runtime.h>
#include <cstdint>

#define FULL_MASK 0xFFFFFFFFu
#define KPL 8                 // timesteps per lane
#define SEG (32 * KPL)        // 256 timesteps per warp-segment
#define WPB 2                 // warps per block
#define PAD_W 9               // padded smem words per lane (conflict-free)

// fast sigmoid via MUFU; rel err ~1e-6, far under 1e-3 tol.
__device__ __forceinline__ float fsigmoid(float x) {
    return __fdividef(1.0f, 1.0f + __expf(-x));
}

__device__ __forceinline__ uint32_t smem_u32(const void* p) {
    return (uint32_t)__cvta_generic_to_shared(p);
}
__device__ __forceinline__ void cp_async16(uint32_t dst, const void* src) {
    asm volatile("cp.async.cg.shared.global [%0], [%1], 16;" :: "r"(dst), "l"(src));
}
__device__ __forceinline__ void cp_async4(uint32_t dst, const void* src) {
    asm volatile("cp.async.ca.shared.global [%0], [%1], 4;" :: "r"(dst), "l"(src));
}
#define CP_COMMIT() asm volatile("cp.async.commit_group;")
#define CP_WAIT1()  asm volatile("cp.async.wait_group 1;")
#define CP_WAIT0()  asm volatile("cp.async.wait_group 0;")

// Precomputed per-timestep lambda and gamma (written by prep_kernel).
__device__ __align__(16) float g_lam_tab[16384];
__device__ float g_gamma_c;

__global__ void prep_kernel(const float* __restrict__ raw_gamma,
                            const float* __restrict__ raw_lambd,
                            const int*   __restrict__ p_start,
                            int T)
{
    int t = blockIdx.x * blockDim.x + threadIdx.x;
    if (t == 0) {
        g_gamma_c = 0.98f + 0.02f * fsigmoid(raw_gamma[0]);  // 0.99+0.01*(2s-1)
    }
    int s0 = p_start ? p_start[0] : 0;
    if (t < T) {
        g_lam_tab[t] = fmaf(0.1f, fsigmoid(raw_lambd[s0 + t]), 0.9f);
    }
}

// One warp per batch row. Backward affine scan:
//   x_t = A_t * x_{t+1} + B_t,   A_t = g*(1-d_t)*l_t  (shared by both recurrences)
// cp.async double-buffered prefetch of r/d/v decouples DRAM latency from the
// serial carry chain with zero register cost.
__global__ __launch_bounds__(WPB * 32)
void td_scan_kernel(const float* __restrict__ values,   // [B, T+1]
                    const float* __restrict__ rewards,  // [B, T]
                    const float* __restrict__ dones,    // [B, T]
                    float* __restrict__ out_lam,        // [B, T+1]
                    float* __restrict__ out_sum,        // [B, T]
                    int B, int T)
{
    // per-warp double buffers
    __shared__ float rbuf[WPB][2][32 * KPL];     // lane-contiguous, 32B stride
    __shared__ float dbuf[WPB][2][32 * KPL];
    __shared__ float vbuf[WPB][2][32 * PAD_W];   // transposed values window

    const int lane = threadIdx.x & 31;
    const int wid  = threadIdx.x >> 5;
    const int row  = blockIdx.x * WPB + wid;
    if (row >= B) return;

    const float g = g_gamma_c;

    const float* vrow = values  + (size_t)row * (size_t)(T + 1);
    const float* rrow = rewards + (size_t)row * (size_t)T;
    const float* drow = dones   + (size_t)row * (size_t)T;
    float* lrow = out_lam + (size_t)row * (size_t)(T + 1);
    float* srow = out_sum + (size_t)row * (size_t)T;

    const float vlast = vrow[T];
    if (lane == 0) lrow[T] = vlast;

    float c_lam = vlast;
    float c_sum = 0.0f;

    const int nseg = (T + SEG - 1) / SEG;

    // ---- issue cp.async prefetch of one full segment into buffer b ----
    auto prefetch = [&](int seg, int b) {
        const int base = seg * SEG + lane * KPL;
        uint32_t rdst = smem_u32(&rbuf[wid][b][lane * KPL]);
        uint32_t ddst = smem_u32(&dbuf[wid][b][lane * KPL]);
        cp_async16(rdst,      rrow + base);
        cp_async16(rdst + 16, rrow + base + 4);
        cp_async16(ddst,      drow + base);
        cp_async16(ddst + 16, drow + base + 4);
        // values window [seg*SEG+1 .. +SEG]: coalesced 4B copies written
        // directly into the transposed (per-lane contiguous, padded) layout.
        const float* vp = vrow + seg * SEG + 1;
        #pragma unroll
        for (int k = 0; k < 8; k++) {
            int i = k * 32 + lane;
            uint32_t vdst = smem_u32(&vbuf[wid][b][(i >> 3) * PAD_W + (i & 7)]);
            cp_async4(vdst, vp + i);
        }
        CP_COMMIT();
    };

    // ---- scan + expand + carry update ----
    auto scan_expand = [&](float A[KPL], float Bl[KPL], float Bs[KPL],
                           float outl[KPL], float outs[KPL]) {
        float SA = A[KPL - 1], SBl = Bl[KPL - 1], SBs = Bs[KPL - 1];
        #pragma unroll
        for (int j = KPL - 2; j >= 0; --j) {
            SBl = fmaf(A[j], SBl, Bl[j]);
            SBs = fmaf(A[j], SBs, Bs[j]);
            SA  = A[j] * SA;
        }
        #pragma unroll
        for (int len = 1; len < 32; len <<= 1) {
            float Ao  = __shfl_down_sync(FULL_MASK, SA,  len);
            float Blo = __shfl_down_sync(FULL_MASK, SBl, len);
            float Bso = __shfl_down_sync(FULL_MASK, SBs, len);
            if (lane + len < 32) {
                SBl = fmaf(SA, Blo, SBl);
                SBs = fmaf(SA, Bso, SBs);
                SA  = SA * Ao;
            }
        }
        float nA  = __shfl_down_sync(FULL_MASK, SA,  1);
        float nBl = __shfl_down_sync(FULL_MASK, SBl, 1);
        float nBs = __shfl_down_sync(FULL_MASK, SBs, 1);
        float xl = (lane == 31) ? c_lam : fmaf(nA, c_lam, nBl);
        float xs = (lane == 31) ? c_sum : fmaf(nA, c_sum, nBs);
        #pragma unroll
        for (int j = KPL - 1; j >= 0; --j) {
            xl = fmaf(A[j], xl, Bl[j]);
            xs = fmaf(A[j], xs, Bs[j]);
            outl[j] = xl;
            outs[j] = xs;
        }
        c_lam = __shfl_sync(FULL_MASK, xl, 0);
        c_sum = __shfl_sync(FULL_MASK, xs, 0);
    };

    int s = nseg - 1;

    // Peel a partial last segment (direct loads; only seg nseg-1 can be partial).
    if (nseg * SEG > T) {
        const int base = s * SEG + lane * KPL;
        float A[KPL], Bl[KPL], Bs[KPL];
        #pragma unroll
        for (int j = 0; j < KPL; j++) {
            int t = base + j;
            if (t < T) {
                float r  = rrow[t];
                float d  = drow[t];
                float vn = vrow[t + 1];
                float l  = g_lam_tab[t];
                float cont = g - g * d;
                A[j]  = cont * l;
                Bl[j] = fmaf(cont - A[j], vn, r);
                Bs[j] = r;
            } else {
                A[j] = 1.0f; Bl[j] = 0.0f; Bs[j] = 0.0f;
            }
        }
        float outl[KPL], outs[KPL];
        scan_expand(A, Bl, Bs, outl, outs);
        #pragma unroll
        for (int j = 0; j < KPL; j++) {
            if (base + j < T) { lrow[base + j] = outl[j]; srow[base + j] = outs[j]; }
        }
        s--;
    }

    if (s < 0) return;

    prefetch(s, 0);
    int cur = 0;

    for (; s >= 0; --s, cur ^= 1) {
        if (s > 0) { prefetch(s - 1, cur ^ 1); CP_WAIT1(); }
        else       { CP_WAIT0(); }
        __syncwarp();

        const int segb = s * SEG;
        const int base = segb + lane * KPL;

        // consume prefetched data
        const float4* r4 = (const float4*)&rbuf[wid][cur][lane * KPL];
        const float4* d4 = (const float4*)&dbuf[wid][cur][lane * KPL];
        float4 ra = r4[0], rb = r4[1];
        float4 da = d4[0], db = d4[1];

        float vn[KPL];
        #pragma unroll
        for (int j = 0; j < KPL; j++) vn[j] = vbuf[wid][cur][lane * PAD_W + j];

        // lambda: L1/L2-hot table (reused by all rows), default caching
        float4 la = *((const float4*)(g_lam_tab + base));
        float4 lb = *((const float4*)(g_lam_tab + base) + 1);

        float r[KPL] = {ra.x, ra.y, ra.z, ra.w, rb.x, rb.y, rb.z, rb.w};
        float d[KPL] = {da.x, da.y, da.z, da.w, db.x, db.y, db.z, db.w};
        float l[KPL] = {la.x, la.y, la.z, la.w, lb.x, lb.y, lb.z, lb.w};

        float A[KPL], Bl[KPL], Bs[KPL];
        #pragma unroll
        for (int j = 0; j < KPL; j++) {
            float cont = g - g * d[j];               // gamma*(1-done)
            A[j]  = cont * l[j];
            Bl[j] = fmaf(cont - A[j], vn[j], r[j]);  // cont*(1-l)*vn + r
            Bs[j] = r[j];
        }

        float outl[KPL], outs[KPL];
        scan_expand(A, Bl, Bs, outl, outs);

        // sum rows aligned -> streaming STG.128
        float4* s4 = (float4*)(srow + base);
        __stcs(s4,     make_float4(outs[0], outs[1], outs[2], outs[3]));
        __stcs(s4 + 1, make_float4(outs[4], outs[5], outs[6], outs[7]));

        // lam rows misaligned -> transpose via the just-consumed v buffer
        __syncwarp();   // all lanes done reading vbuf[cur]
        #pragma unroll
        for (int j = 0; j < KPL; j++) vbuf[wid][cur][lane * PAD_W + j] = outl[j];
        __syncwarp();
        float* lp = lrow + segb;
        #pragma unroll
        for (int k = 0; k < 8; k++) {
            int i = k * 32 + lane;
            __stcs(lp + i, vbuf[wid][cur][(i >> 3) * PAD_W + (i & 7)]);
        }
        __syncwarp();   // staging reads done before next prefetch reuses buffer
    }
}

extern "C" void kernel_launch(void* const* d_in, const int* in_sizes, int n_in,
                              void* d_out, int out_size)
{
    const float* values    = (const float*)d_in[0];
    const float* rewards   = (const float*)d_in[1];
    const float* dones     = (const float*)d_in[2];
    const float* raw_gamma = (const float*)d_in[3];
    const float* raw_lambd = (const float*)d_in[4];
    const int*   p_start   = (n_in > 5) ? (const int*)d_in[5] : nullptr;

    const int T = in_sizes[4];
    const int B = in_sizes[1] / T;

    float* out_lam = (float*)d_out;                       // B*(T+1)
    float* out_sum = (float*)d_out + (size_t)B * (T + 1); // B*T

    prep_kernel<<<(T + 255) / 256, 256>>>(raw_gamma, raw_lambd, p_start, T);

    const int threads = WPB * 32;
    const int blocks  = (B + WPB - 1) / WPB;

    td_scan_kernel<<<blocks, threads>>>(
        values, rewards, dones, out_lam, out_sum, B, T);
}